// round 8
// baseline (speedup 1.0000x reference)
#include <cuda_runtime.h>
#include <cuda_bf16.h>
#include <cstdint>
#include <math.h>

// Problem constants
#define B_      32
#define C_      256
#define HW_     4096
#define HEADS_  4
#define DH_     32
#define HID_    128
#define QKV_C   384
#define NMEM_   4
#define NTOT_   4100
#define NCOLS_  (B_*HW_)
#define NROWS_K (B_*HEADS_*DH_)
#define NSPLIT_ 8

// ---------------- scratch (static device arrays) ----------------
__device__ __align__(16) __nv_bfloat16 g_w1hi[QKV_C * C_];
__device__ __align__(16) __nv_bfloat16 g_w1lo[QKV_C * C_];
__device__ __align__(16) __nv_bfloat16 g_w2hi[C_ * HID_];
__device__ __align__(16) __nv_bfloat16 g_w2lo[C_ * HID_];
__device__ __align__(16) __nv_bfloat16 g_xThi[(size_t)B_ * HW_ * C_];   // x^T [b][hw][c]
__device__ __align__(16) __nv_bfloat16 g_xTlo[(size_t)B_ * HW_ * C_];
__device__ __align__(16) __nv_bfloat16 g_aThi[(size_t)B_ * HW_ * HID_]; // att [b][h][hw][dh]
__device__ __align__(16) __nv_bfloat16 g_aTlo[(size_t)B_ * HW_ * HID_];
__device__ float g_invs[NCOLS_];
__device__ float g_qkv[(size_t)B_ * QKV_C * HW_];
__device__ float g_kmax[NROWS_K];
__device__ float g_kinv[NROWS_K];
__device__ float g_ctxp[(size_t)NSPLIT_ * B_ * HEADS_ * DH_ * DH_];
__device__ float g_ctx[(size_t)B_ * HEADS_ * DH_ * DH_];
__device__ float g_o[(size_t)B_ * C_ * HW_];

// ---------------- asm helpers ----------------
__device__ __forceinline__ uint32_t smem_u32(const void* p) {
    uint32_t a;
    asm("{ .reg .u64 t; cvta.to.shared.u64 t, %1; cvt.u32.u64 %0, t; }" : "=r"(a) : "l"(p));
    return a;
}
#define CP16(sa, gp) asm volatile("cp.async.cg.shared.global [%0], [%1], 16;" :: "r"(sa), "l"(gp))
#define CP_COMMIT()  asm volatile("cp.async.commit_group;" ::: "memory")
#define CP_WAIT1()   asm volatile("cp.async.wait_group 1;" ::: "memory")
#define CP_WAIT0()   asm volatile("cp.async.wait_group 0;" ::: "memory")
#define LDMX4(r, a) asm volatile("ldmatrix.sync.aligned.m8n8.x4.shared.b16 {%0,%1,%2,%3}, [%4];" \
    : "=r"((r)[0]), "=r"((r)[1]), "=r"((r)[2]), "=r"((r)[3]) : "r"(a))
#define LDMX2(r, a) asm volatile("ldmatrix.sync.aligned.m8n8.x2.shared.b16 {%0,%1}, [%2];" \
    : "=r"((r)[0]), "=r"((r)[1]) : "r"(a))

// ---------------- prep: split weights into bf16 hi/lo ----------------
__global__ void prep_w1(const float* __restrict__ w, const float* __restrict__ g1) {
    int idx = blockIdx.x * blockDim.x + threadIdx.x;
    if (idx < QKV_C * C_) {
        float v = w[idx] * g1[idx & (C_ - 1)] * 16.0f;
        __nv_bfloat16 h = __float2bfloat16(v);
        g_w1hi[idx] = h;
        g_w1lo[idx] = __float2bfloat16(v - __bfloat162float(h));
    }
}
__global__ void prep_w2(const float* __restrict__ w) {
    int idx = blockIdx.x * blockDim.x + threadIdx.x;
    if (idx < C_ * HID_) {
        float v = w[idx];
        __nv_bfloat16 h = __float2bfloat16(v);
        g_w2hi[idx] = h;
        g_w2lo[idx] = __float2bfloat16(v - __bfloat162float(h));
    }
}

// ---------------- transpose + hi/lo split: x[b][c][hw] -> xT[b][hw][c] ------
__global__ void transpose_split(const float* __restrict__ x) {
    __shared__ float tile[32][33];
    int bx = blockIdx.x, by = blockIdx.y, bz = blockIdx.z;
    int tx = threadIdx.x, ty = threadIdx.y;   // (32, 8)
    const float* xp = x + (size_t)bz * C_ * HW_;
    #pragma unroll
    for (int it = 0; it < 4; it++) {
        int c = by * 32 + ty + it * 8;
        tile[ty + it * 8][tx] = xp[(size_t)c * HW_ + bx * 32 + tx];
    }
    __syncthreads();
    #pragma unroll
    for (int it = 0; it < 4; it++) {
        int hwl = ty + it * 8;
        float v = tile[tx][hwl];
        __nv_bfloat16 h = __float2bfloat16(v);
        size_t o = ((size_t)bz * HW_ + bx * 32 + hwl) * C_ + by * 32 + tx;
        g_xThi[o] = h;
        g_xTlo[o] = __float2bfloat16(v - __bfloat162float(h));
    }
}

// ------------- colnorm from transposed bf16 hi/lo (warp per row) -----------
__global__ void colnorm2() {
    int row = blockIdx.x * 8 + (threadIdx.x >> 5);
    int lane = threadIdx.x & 31;
    const __nv_bfloat16* ph = g_xThi + (size_t)row * C_ + lane * 8;
    const __nv_bfloat16* pl = g_xTlo + (size_t)row * C_ + lane * 8;
    uint4 uh = *(const uint4*)ph;
    uint4 ul = *(const uint4*)pl;
    float ss = 0.f;
    const uint32_t* hh = (const uint32_t*)&uh;
    const uint32_t* ll = (const uint32_t*)&ul;
    #pragma unroll
    for (int i = 0; i < 4; i++) {
        __nv_bfloat162 h2 = *(__nv_bfloat162*)&hh[i];
        __nv_bfloat162 l2 = *(__nv_bfloat162*)&ll[i];
        float a = __bfloat162float(h2.x) + __bfloat162float(l2.x);
        float b = __bfloat162float(h2.y) + __bfloat162float(l2.y);
        ss += a * a + b * b;
    }
    #pragma unroll
    for (int s = 16; s > 0; s >>= 1) ss += __shfl_xor_sync(0xffffffff, ss, s);
    if (lane == 0) g_invs[row] = 1.0f / fmaxf(sqrtf(ss), 1e-12f);
}

// ---------------- tiny instrumentation/zero kernel (launch index 4) --------
__global__ void zero_ctx() {
    int i = blockIdx.x * blockDim.x + threadIdx.x;
    if (i < B_ * HEADS_ * DH_ * DH_) g_ctx[i] = 0.f;
}

// ================= mma.sync bf16 GEMM, 2-stage cp.async + ldmatrix ==========
__device__ __forceinline__ void mma16816(float* d, const uint32_t* a, const uint32_t* b) {
    asm volatile(
        "mma.sync.aligned.m16n8k16.row.col.f32.bf16.bf16.f32 "
        "{%0,%1,%2,%3}, {%4,%5,%6,%7}, {%8,%9}, {%0,%1,%2,%3};"
        : "+f"(d[0]), "+f"(d[1]), "+f"(d[2]), "+f"(d[3])
        : "r"(a[0]), "r"(a[1]), "r"(a[2]), "r"(a[3]), "r"(b[0]), "r"(b[1]));
}

#define SAPAD 40                       // halves per 32-wide row: 80B rows, 16B-aligned
#define TILE_H (128 * SAPAD)
#define TILE_B (TILE_H * 2)            // 10240 bytes
#define STAGE_B (TILE_B * 4)           // Ahi,Alo,Bhi,Blo = 40960 bytes
#define GSMEM_B (STAGE_B * 2)          // 81920 bytes -> 2 CTAs/SM fits in 228KB

__global__ void __launch_bounds__(256, 2)
gemm_mma(const __nv_bfloat16* __restrict__ Ahi, const __nv_bfloat16* __restrict__ Alo,
         const __nv_bfloat16* __restrict__ BThi, const __nv_bfloat16* __restrict__ BTlo,
         float* __restrict__ Cg, int K, int rsA, int rsB, long csB,
         long strideB, long strideC,
         const float* __restrict__ colscale, const float* __restrict__ bias)
{
    extern __shared__ __align__(16) char smem[];
    int tid = threadIdx.x, wid = tid >> 5, lane = tid & 31;
    int wm = wid >> 2, wn = wid & 3;
    int grp = lane >> 2, qp = lane & 3;
    int nBase = blockIdx.x * 128, mBase = blockIdx.y * 128, z = blockIdx.z;
    const __nv_bfloat16* Bhp = BThi + (long)z * strideB;
    const __nv_bfloat16* Blp = BTlo + (long)z * strideB;
    float* Cp = Cg + (long)z * strideC;

    uint32_t sbase = smem_u32(smem);
    int r0i = tid >> 2, sg0 = tid & 3;
    int r1i = (tid + 256) >> 2;

    uint32_t aOff = (uint32_t)((wm * 64 + (lane & 15)) * SAPAD + (lane >> 4) * 8) * 2;
    uint32_t bOff = (uint32_t)((wn * 32 + (lane & 7)) * SAPAD + ((lane >> 3) & 1) * 8) * 2;

    float acc[4][4][4];
    #pragma unroll
    for (int i = 0; i < 4; i++)
        #pragma unroll
        for (int j = 0; j < 4; j++)
            #pragma unroll
            for (int k = 0; k < 4; k++) acc[i][j][k] = 0.f;

    int nk = K / 32;

    auto load_stage = [&](int stage, int kc) {
        uint32_t st = sbase + stage * STAGE_B;
        #pragma unroll
        for (int t = 0; t < 2; t++) {
            int r = t ? r1i : r0i;
            int sg = sg0;
            uint32_t so = (uint32_t)(r * SAPAD + sg * 8) * 2;
            const __nv_bfloat16* gA = Ahi + (long)(mBase + r) * rsA + kc + sg * 8;
            const __nv_bfloat16* gAl = Alo + (long)(mBase + r) * rsA + kc + sg * 8;
            long bo = (long)(nBase + r) * rsB + (long)kc * csB + sg * 8;
            CP16(st + so, gA);
            CP16(st + TILE_B + so, gAl);
            CP16(st + 2 * TILE_B + so, Bhp + bo);
            CP16(st + 3 * TILE_B + so, Blp + bo);
        }
    };

    load_stage(0, 0);
    CP_COMMIT();

    for (int ck = 0; ck < nk; ck++) {
        int s = ck & 1;
        if (ck + 1 < nk) {
            load_stage(1 - s, (ck + 1) * 32);
            CP_COMMIT();
            CP_WAIT1();
        } else {
            CP_WAIT0();
        }
        __syncthreads();

        uint32_t st = sbase + s * STAGE_B;
        uint32_t aHiA = st + aOff;
        uint32_t aLoA = aHiA + TILE_B;
        uint32_t bHiA = st + 2 * TILE_B + bOff;
        uint32_t bLoA = bHiA + TILE_B;

        #pragma unroll
        for (int ks = 0; ks < 2; ks++) {
            uint32_t ko = ks * 32;   // bytes
            uint32_t ahi[4][4], alo[4][4], bhi[4][2], blo[4][2];
            #pragma unroll
            for (int mt = 0; mt < 4; mt++) {
                uint32_t ad = mt * (16 * SAPAD * 2) + ko;
                LDMX4(ahi[mt], aHiA + ad);
                LDMX4(alo[mt], aLoA + ad);
            }
            #pragma unroll
            for (int nt = 0; nt < 4; nt++) {
                uint32_t bd = nt * (8 * SAPAD * 2) + ko;
                LDMX2(bhi[nt], bHiA + bd);
                LDMX2(blo[nt], bLoA + bd);
            }
            #pragma unroll
            for (int mt = 0; mt < 4; mt++)
                #pragma unroll
                for (int nt = 0; nt < 4; nt++)
                    mma16816(acc[mt][nt], ahi[mt], bhi[nt]);
            #pragma unroll
            for (int mt = 0; mt < 4; mt++)
                #pragma unroll
                for (int nt = 0; nt < 4; nt++)
                    mma16816(acc[mt][nt], ahi[mt], blo[nt]);
            #pragma unroll
            for (int mt = 0; mt < 4; mt++)
                #pragma unroll
                for (int nt = 0; nt < 4; nt++)
                    mma16816(acc[mt][nt], alo[mt], bhi[nt]);
        }
        __syncthreads();
    }

    // epilogue
    #pragma unroll
    for (int mt = 0; mt < 4; mt++) {
        #pragma unroll
        for (int nt = 0; nt < 4; nt++) {
            int m0 = mBase + wm * 64 + mt * 16 + grp;
            int n0 = nBase + wn * 32 + nt * 8 + qp * 2;
            float* a = acc[mt][nt];
            float2 v0 = make_float2(a[0], a[1]);
            float2 v1 = make_float2(a[2], a[3]);
            if (bias) {
                float b0 = bias[m0], b1 = bias[m0 + 8];
                v0.x += b0; v0.y += b0; v1.x += b1; v1.y += b1;
            }
            if (colscale) {
                float c0 = colscale[(long)z * HW_ + n0];
                float c1 = colscale[(long)z * HW_ + n0 + 1];
                v0.x *= c0; v0.y *= c1; v1.x *= c0; v1.y *= c1;
            }
            *(float2*)(Cp + (long)m0 * HW_ + n0) = v0;
            *(float2*)(Cp + (long)(m0 + 8) * HW_ + n0) = v1;
        }
    }
}

// ---------------- k softmax stats ----------------
__global__ void kstats(const float* __restrict__ memkv) {
    int r = blockIdx.x;
    int b = r >> 7, hd = r & 127;
    int h = hd >> 5, d = hd & 31;
    const float* kp = g_qkv + ((size_t)b * QKV_C + HID_ + hd) * HW_;
    const float* mp = memkv + (h * DH_ + d) * NMEM_;
    int tid = threadIdx.x;
    __shared__ float red[128];
    float m = -1e30f;
    for (int i = tid; i < NTOT_; i += 128) {
        float v = (i < NMEM_) ? mp[i] : kp[i - NMEM_];
        m = fmaxf(m, v);
    }
    red[tid] = m; __syncthreads();
    for (int s = 64; s > 0; s >>= 1) {
        if (tid < s) red[tid] = fmaxf(red[tid], red[tid + s]);
        __syncthreads();
    }
    m = red[0]; __syncthreads();
    float sum = 0.f;
    for (int i = tid; i < NTOT_; i += 128) {
        float v = (i < NMEM_) ? mp[i] : kp[i - NMEM_];
        sum += __expf(v - m);
    }
    red[tid] = sum; __syncthreads();
    for (int s = 64; s > 0; s >>= 1) {
        if (tid < s) red[tid] += red[tid + s];
        __syncthreads();
    }
    if (tid == 0) { g_kmax[r] = m; g_kinv[r] = 1.0f / red[0]; }
}

// ---------------- context partials ----------------
__global__ void ctx_kernel(const float* __restrict__ memkv) {
    int bh = blockIdx.x;
    int split = blockIdx.y;
    int b = bh >> 2, h = bh & 3;
    int tid = threadIdx.x;
    __shared__ float ks[DH_][65];
    __shared__ float vs[DH_][65];
    int e = tid & 31, dg = tid >> 5;
    float acc[4] = {0.f, 0.f, 0.f, 0.f};
    const float* kbase = g_qkv + ((size_t)b * QKV_C + HID_ + h * DH_) * HW_;
    const float* vbase = g_qkv + ((size_t)b * QKV_C + 2 * HID_ + h * DH_) * HW_;
    int rbase = bh * DH_;
    int n0beg = split * 512;
    for (int n0 = n0beg; n0 < n0beg + 512; n0 += 64) {
        #pragma unroll
        for (int t = 0; t < 8; t++) {
            int i = tid + t * 256;
            int d = i >> 6, j = i & 63;
            float kv = kbase[(size_t)d * HW_ + n0 + j];
            ks[d][j] = __expf(kv - g_kmax[rbase + d]) * g_kinv[rbase + d];
            vs[d][j] = vbase[(size_t)d * HW_ + n0 + j];
        }
        __syncthreads();
        #pragma unroll 4
        for (int j = 0; j < 64; j++) {
            float vv = vs[e][j];
            #pragma unroll
            for (int dd = 0; dd < 4; dd++)
                acc[dd] += ks[dg + dd * 8][j] * vv;
        }
        __syncthreads();
    }
    if (split == 0) {
        #pragma unroll
        for (int j = 0; j < NMEM_; j++) {
            #pragma unroll
            for (int dd = 0; dd < 4; dd++) {
                int d = dg + dd * 8;
                float kk = __expf(memkv[(h * DH_ + d) * NMEM_ + j] - g_kmax[rbase + d]) * g_kinv[rbase + d];
                float vv = memkv[((HEADS_ + h) * DH_ + e) * NMEM_ + j];
                acc[dd] += kk * vv;
            }
        }
    }
    #pragma unroll
    for (int dd = 0; dd < 4; dd++) {
        int d = dg + dd * 8;
        g_ctxp[(size_t)split * (B_ * HEADS_ * DH_ * DH_) + bh * 1024 + d * 32 + e] = acc[dd];
    }
}

__global__ void ctx_reduce() {
    int i = blockIdx.x * blockDim.x + threadIdx.x;
    if (i >= B_ * HEADS_ * DH_ * DH_) return;
    float s = 0.f;
    #pragma unroll
    for (int t = 0; t < NSPLIT_; t++) s += g_ctxp[(size_t)t * (B_ * HEADS_ * DH_ * DH_) + i];
    g_ctx[i] = s;
}

// -------- q softmax + apply context; writes att [b][h][hw][dh] hi/lo --------
__global__ void apply_ctx() {
    int bh = blockIdx.y;
    int b = bh >> 2, h = bh & 3;
    int n = blockIdx.x * 128 + threadIdx.x;
    __shared__ float cs[DH_][DH_ + 1];
    for (int i = threadIdx.x; i < DH_ * DH_; i += 128)
        cs[i >> 5][i & 31] = g_ctx[bh * 1024 + i];
    __syncthreads();
    const float* qp = g_qkv + ((size_t)b * QKV_C + h * DH_) * HW_ + n;
    float qd[DH_];
    float m = -1e30f;
    #pragma unroll
    for (int d = 0; d < DH_; d++) { qd[d] = qp[(size_t)d * HW_]; m = fmaxf(m, qd[d]); }
    float s = 0.f;
    #pragma unroll
    for (int d = 0; d < DH_; d++) { qd[d] = __expf(qd[d] - m); s += qd[d]; }
    float inv = 0.17677669529663687f / s;
    #pragma unroll
    for (int d = 0; d < DH_; d++) qd[d] *= inv;

    uint32_t hiP[16], loP[16];
    #pragma unroll
    for (int ep = 0; ep < 16; ep++) {
        float o0 = 0.f, o1 = 0.f;
        #pragma unroll
        for (int d = 0; d < DH_; d++) {
            o0 += cs[d][2 * ep] * qd[d];
            o1 += cs[d][2 * ep + 1] * qd[d];
        }
        __nv_bfloat162 h2 = __floats2bfloat162_rn(o0, o1);
        hiP[ep] = *(uint32_t*)&h2;
        float r0 = o0 - __bfloat162float(h2.x);
        float r1 = o1 - __bfloat162float(h2.y);
        __nv_bfloat162 l2 = __floats2bfloat162_rn(r0, r1);
        loP[ep] = *(uint32_t*)&l2;
    }
    size_t base = (((size_t)b * HEADS_ + h) * HW_ + n) * DH_;
    #pragma unroll
    for (int t = 0; t < 4; t++) {
        *(uint4*)(g_aThi + base + t * 8) = *(uint4*)(hiP + t * 4);
        *(uint4*)(g_aTlo + base + t * 8) = *(uint4*)(loP + t * 4);
    }
}

// ---------------- final rms norm ----------------
__global__ void rmsnorm2(const float* __restrict__ g2, float* __restrict__ out) {
    int idx = blockIdx.x * blockDim.x + threadIdx.x;
    if (idx >= NCOLS_) return;
    int b = idx >> 12, hw = idx & (HW_ - 1);
    const float* p = g_o + (size_t)b * C_ * HW_ + hw;
    float ss = 0.f;
    #pragma unroll 8
    for (int c = 0; c < C_; c++) { float v = p[(size_t)c * HW_]; ss += v * v; }
    float sc = 16.0f / fmaxf(sqrtf(ss), 1e-12f);
    float* q = out + (size_t)b * C_ * HW_ + hw;
    #pragma unroll 8
    for (int c = 0; c < C_; c++) q[(size_t)c * HW_] = p[(size_t)c * HW_] * sc * g2[c];
}

// ---------------- launcher ----------------
extern "C" void kernel_launch(void* const* d_in, const int* in_sizes, int n_in,
                              void* d_out, int out_size) {
    const float* x      = (const float*)d_in[0];
    const float* g1     = (const float*)d_in[1];
    const float* mem_kv = (const float*)d_in[2];
    const float* w_qkv  = (const float*)d_in[3];
    const float* w_out  = (const float*)d_in[4];
    const float* b_out  = (const float*)d_in[5];
    const float* g2     = (const float*)d_in[6];
    float* out = (float*)d_out;

    __nv_bfloat16 *w1hi, *w1lo, *w2hi, *w2lo, *xThi, *xTlo, *aThi, *aTlo;
    float *invs, *qkv, *o;
    cudaGetSymbolAddress((void**)&w1hi, g_w1hi);
    cudaGetSymbolAddress((void**)&w1lo, g_w1lo);
    cudaGetSymbolAddress((void**)&w2hi, g_w2hi);
    cudaGetSymbolAddress((void**)&w2lo, g_w2lo);
    cudaGetSymbolAddress((void**)&xThi, g_xThi);
    cudaGetSymbolAddress((void**)&xTlo, g_xTlo);
    cudaGetSymbolAddress((void**)&aThi, g_aThi);
    cudaGetSymbolAddress((void**)&aTlo, g_aTlo);
    cudaGetSymbolAddress((void**)&invs, g_invs);
    cudaGetSymbolAddress((void**)&qkv,  g_qkv);
    cudaGetSymbolAddress((void**)&o,    g_o);

    cudaFuncSetAttribute(gemm_mma, cudaFuncAttributeMaxDynamicSharedMemorySize, GSMEM_B);

    prep_w1<<<(QKV_C * C_ + 255) / 256, 256>>>(w_qkv, g1);                 // launch 0
    prep_w2<<<(C_ * HID_ + 255) / 256, 256>>>(w_out);                      // launch 1
    transpose_split<<<dim3(HW_ / 32, C_ / 32, B_), dim3(32, 8)>>>(x);      // launch 2
    colnorm2<<<NCOLS_ / 8, 256>>>();                                       // launch 3
    zero_ctx<<<(B_ * HEADS_ * DH_ * DH_ + 255) / 256, 256>>>();            // launch 4 (instrumentation)
    gemm_mma<<<dim3(HW_ / 128, QKV_C / 128, B_), 256, GSMEM_B>>>(          // launch 5 -> ncu target
        w1hi, w1lo, xThi, xTlo, qkv, C_, C_, C_, 1L,
        (long)HW_ * C_, (long)QKV_C * HW_, invs, nullptr);
    kstats<<<NROWS_K, 128>>>(mem_kv);
    ctx_kernel<<<dim3(B_ * HEADS_, NSPLIT_), 256>>>(mem_kv);
    ctx_reduce<<<(B_ * HEADS_ * DH_ * DH_ + 255) / 256, 256>>>();
    apply_ctx<<<dim3(HW_ / 128, B_ * HEADS_), 128>>>();
    gemm_mma<<<dim3(HW_ / 128, C_ / 128, B_), 256, GSMEM_B>>>(
        w2hi, w2lo, aThi, aTlo, o, HID_, HID_, DH_, (long)HW_,
        (long)HW_ * HID_, (long)C_ * HW_, nullptr, b_out);
    rmsnorm2<<<(NCOLS_ + 255) / 256, 256>>>(g2, out);
}

// round 13
// speedup vs baseline: 1.1720x; 1.1720x over previous
#include <cuda_runtime.h>
#include <cuda_fp16.h>
#include <cstdint>
#include <math.h>

// Problem constants
#define B_      32
#define C_      256
#define HW_     4096
#define HEADS_  4
#define DH_     32
#define HID_    128
#define QKV_C   384
#define NMEM_   4
#define NTOT_   4100
#define NCOLS_  (B_*HW_)
#define NROWS_K (B_*HEADS_*DH_)
#define NSPLIT_ 8

// ---------------- scratch (static device arrays) ----------------
__device__ __align__(16) __half g_w1hi[QKV_C * C_];
__device__ __align__(16) __half g_w1lo[QKV_C * C_];
__device__ __align__(16) __half g_w2hi[C_ * HID_];
__device__ __align__(16) __half g_w2lo[C_ * HID_];
__device__ __align__(16) __half g_xTf[(size_t)B_ * HW_ * C_];    // x^T [b][hw][c] fp16
__device__ __align__(16) __half g_aTf[(size_t)B_ * HW_ * HID_];  // att [b][h][hw][dh] fp16
__device__ float g_invs[NCOLS_];
__device__ float g_qkv[(size_t)B_ * QKV_C * HW_];
__device__ float g_kmax[NROWS_K];
__device__ float g_kinv[NROWS_K];
__device__ float g_ctxp[(size_t)NSPLIT_ * B_ * HEADS_ * DH_ * DH_];
__device__ float g_ctx[(size_t)B_ * HEADS_ * DH_ * DH_];
__device__ float g_o[(size_t)B_ * C_ * HW_];

// ---------------- asm helpers ----------------
__device__ __forceinline__ uint32_t smem_u32(const void* p) {
    uint32_t a;
    asm("{ .reg .u64 t; cvta.to.shared.u64 t, %1; cvt.u32.u64 %0, t; }" : "=r"(a) : "l"(p));
    return a;
}
#define CP16(sa, gp) asm volatile("cp.async.cg.shared.global [%0], [%1], 16;" :: "r"(sa), "l"(gp))
#define CP_COMMIT()  asm volatile("cp.async.commit_group;" ::: "memory")
#define CP_WAIT1()   asm volatile("cp.async.wait_group 1;" ::: "memory")
#define CP_WAIT0()   asm volatile("cp.async.wait_group 0;" ::: "memory")
#define LDMX4(r, a) asm volatile("ldmatrix.sync.aligned.m8n8.x4.shared.b16 {%0,%1,%2,%3}, [%4];" \
    : "=r"((r)[0]), "=r"((r)[1]), "=r"((r)[2]), "=r"((r)[3]) : "r"(a))
#define LDMX2(r, a) asm volatile("ldmatrix.sync.aligned.m8n8.x2.shared.b16 {%0,%1}, [%2];" \
    : "=r"((r)[0]), "=r"((r)[1]) : "r"(a))

// ---------------- prep: split weights into fp16 hi/lo ----------------
__global__ void prep_w1(const float* __restrict__ w, const float* __restrict__ g1) {
    int idx = blockIdx.x * blockDim.x + threadIdx.x;
    if (idx < QKV_C * C_) {
        float v = w[idx] * g1[idx & (C_ - 1)] * 16.0f;
        __half h = __float2half_rn(v);
        g_w1hi[idx] = h;
        g_w1lo[idx] = __float2half_rn(v - __half2float(h));
    }
}
__global__ void prep_w2(const float* __restrict__ w) {
    int idx = blockIdx.x * blockDim.x + threadIdx.x;
    if (idx < C_ * HID_) {
        float v = w[idx];
        __half h = __float2half_rn(v);
        g_w2hi[idx] = h;
        g_w2lo[idx] = __float2half_rn(v - __half2float(h));
    }
}

// ------- transpose x -> xT fp16 [b][hw][c], fused per-column L2 norm -------
__global__ void transpose_norm(const float* __restrict__ x) {
    __shared__ float tile[32][33];
    __shared__ float ssp[8][33];
    int bx = blockIdx.x, bz = blockIdx.y;
    int tx = threadIdx.x, ty = threadIdx.y;   // (32, 8)
    const float* xp = x + (size_t)bz * C_ * HW_;
    float ss = 0.f;
    for (int cc = 0; cc < 8; cc++) {
        #pragma unroll
        for (int it = 0; it < 4; it++) {
            int c = cc * 32 + ty + it * 8;
            float v = xp[(size_t)c * HW_ + bx * 32 + tx];
            tile[ty + it * 8][tx] = v;
            ss += v * v;                         // thread tx accumulates for hw=bx*32+tx
        }
        __syncthreads();
        #pragma unroll
        for (int it = 0; it < 4; it++) {
            int hwl = ty + it * 8;
            float v = tile[tx][hwl];
            size_t o = ((size_t)bz * HW_ + bx * 32 + hwl) * C_ + cc * 32 + tx;
            g_xTf[o] = __float2half_rn(v);
        }
        __syncthreads();
    }
    ssp[ty][tx] = ss;
    __syncthreads();
    if (ty == 0) {
        float t = 0.f;
        #pragma unroll
        for (int j = 0; j < 8; j++) t += ssp[j][tx];
        g_invs[bz * HW_ + bx * 32 + tx] = 1.0f / fmaxf(sqrtf(t), 1e-12f);
    }
}

// ========== mma.sync fp16 GEMM, 2-pass (A exact hi/lo, B rounded) ==========
__device__ __forceinline__ void mma16816(float* d, const uint32_t* a, const uint32_t* b) {
    asm volatile(
        "mma.sync.aligned.m16n8k16.row.col.f32.f16.f16.f32 "
        "{%0,%1,%2,%3}, {%4,%5,%6,%7}, {%8,%9}, {%0,%1,%2,%3};"
        : "+f"(d[0]), "+f"(d[1]), "+f"(d[2]), "+f"(d[3])
        : "r"(a[0]), "r"(a[1]), "r"(a[2]), "r"(a[3]), "r"(b[0]), "r"(b[1]));
}

#define SAPAD 40                       // halves per 32-wide row: 80B rows, 16B-aligned
#define TILE_H (128 * SAPAD)
#define TILE_B (TILE_H * 2)            // 10240 bytes
#define STAGE_B (TILE_B * 3)           // Ahi, Alo, Bf = 30720 bytes
#define GSMEM_B (STAGE_B * 2)          // 61440 bytes

__global__ void __launch_bounds__(256)
gemm_mma(const __half* __restrict__ Ahi, const __half* __restrict__ Alo,
         const __half* __restrict__ BTf, float* __restrict__ Cg,
         int K, int rsA, int rsB, long csB,
         long strideB, long strideC,
         const float* __restrict__ colscale, const float* __restrict__ bias)
{
    extern __shared__ __align__(16) char smem[];
    int tid = threadIdx.x, wid = tid >> 5, lane = tid & 31;
    int wm = wid >> 2, wn = wid & 3;
    int grp = lane >> 2, qp = lane & 3;
    int nBase = blockIdx.x * 128, mBase = blockIdx.y * 128, z = blockIdx.z;
    const __half* Bp = BTf + (long)z * strideB;
    float* Cp = Cg + (long)z * strideC;

    uint32_t sbase = smem_u32(smem);
    int r0i = tid >> 2, sg0 = tid & 3;
    int r1i = (tid + 256) >> 2;

    uint32_t aOff = (uint32_t)((wm * 64 + (lane & 15)) * SAPAD + (lane >> 4) * 8) * 2;
    uint32_t bOff = (uint32_t)((wn * 32 + (lane & 7)) * SAPAD + ((lane >> 3) & 1) * 8) * 2;

    float acc[4][4][4];
    #pragma unroll
    for (int i = 0; i < 4; i++)
        #pragma unroll
        for (int j = 0; j < 4; j++)
            #pragma unroll
            for (int k = 0; k < 4; k++) acc[i][j][k] = 0.f;

    int nk = K / 32;

    auto load_stage = [&](int stage, int kc) {
        uint32_t st = sbase + stage * STAGE_B;
        #pragma unroll
        for (int t = 0; t < 2; t++) {
            int r = t ? r1i : r0i;
            int sg = sg0;
            uint32_t so = (uint32_t)(r * SAPAD + sg * 8) * 2;
            const __half* gA = Ahi + (long)(mBase + r) * rsA + kc + sg * 8;
            const __half* gAl = Alo + (long)(mBase + r) * rsA + kc + sg * 8;
            long bo = (long)(nBase + r) * rsB + (long)kc * csB + sg * 8;
            CP16(st + so, gA);
            CP16(st + TILE_B + so, gAl);
            CP16(st + 2 * TILE_B + so, Bp + bo);
        }
    };

    load_stage(0, 0);
    CP_COMMIT();

    for (int ck = 0; ck < nk; ck++) {
        int s = ck & 1;
        if (ck + 1 < nk) {
            load_stage(1 - s, (ck + 1) * 32);
            CP_COMMIT();
            CP_WAIT1();
        } else {
            CP_WAIT0();
        }
        __syncthreads();

        uint32_t st = sbase + s * STAGE_B;
        uint32_t aHiA = st + aOff;
        uint32_t aLoA = aHiA + TILE_B;
        uint32_t bA = st + 2 * TILE_B + bOff;

        #pragma unroll
        for (int ks = 0; ks < 2; ks++) {
            uint32_t ko = ks * 32;   // bytes
            uint32_t ahi[4][4], alo[4][4], bf[4][2];
            #pragma unroll
            for (int mt = 0; mt < 4; mt++) {
                uint32_t ad = mt * (16 * SAPAD * 2) + ko;
                LDMX4(ahi[mt], aHiA + ad);
                LDMX4(alo[mt], aLoA + ad);
            }
            #pragma unroll
            for (int nt = 0; nt < 4; nt++) {
                uint32_t bd = nt * (8 * SAPAD * 2) + ko;
                LDMX2(bf[nt], bA + bd);
            }
            #pragma unroll
            for (int mt = 0; mt < 4; mt++)
                #pragma unroll
                for (int nt = 0; nt < 4; nt++)
                    mma16816(acc[mt][nt], ahi[mt], bf[nt]);
            #pragma unroll
            for (int mt = 0; mt < 4; mt++)
                #pragma unroll
                for (int nt = 0; nt < 4; nt++)
                    mma16816(acc[mt][nt], alo[mt], bf[nt]);
        }
        __syncthreads();
    }

    // epilogue
    #pragma unroll
    for (int mt = 0; mt < 4; mt++) {
        #pragma unroll
        for (int nt = 0; nt < 4; nt++) {
            int m0 = mBase + wm * 64 + mt * 16 + grp;
            int n0 = nBase + wn * 32 + nt * 8 + qp * 2;
            float* a = acc[mt][nt];
            float2 v0 = make_float2(a[0], a[1]);
            float2 v1 = make_float2(a[2], a[3]);
            if (bias) {
                float b0 = bias[m0], b1 = bias[m0 + 8];
                v0.x += b0; v0.y += b0; v1.x += b1; v1.y += b1;
            }
            if (colscale) {
                float c0 = colscale[(long)z * HW_ + n0];
                float c1 = colscale[(long)z * HW_ + n0 + 1];
                v0.x *= c0; v0.y *= c1; v1.x *= c0; v1.y *= c1;
            }
            *(float2*)(Cp + (long)m0 * HW_ + n0) = v0;
            *(float2*)(Cp + (long)(m0 + 8) * HW_ + n0) = v1;
        }
    }
}

// ---------------- k softmax stats ----------------
__global__ void kstats(const float* __restrict__ memkv) {
    int r = blockIdx.x;
    int b = r >> 7, hd = r & 127;
    int h = hd >> 5, d = hd & 31;
    const float* kp = g_qkv + ((size_t)b * QKV_C + HID_ + hd) * HW_;
    const float* mp = memkv + (h * DH_ + d) * NMEM_;
    int tid = threadIdx.x;
    __shared__ float red[128];
    float m = -1e30f;
    for (int i = tid; i < NTOT_; i += 128) {
        float v = (i < NMEM_) ? mp[i] : kp[i - NMEM_];
        m = fmaxf(m, v);
    }
    red[tid] = m; __syncthreads();
    for (int s = 64; s > 0; s >>= 1) {
        if (tid < s) red[tid] = fmaxf(red[tid], red[tid + s]);
        __syncthreads();
    }
    m = red[0]; __syncthreads();
    float sum = 0.f;
    for (int i = tid; i < NTOT_; i += 128) {
        float v = (i < NMEM_) ? mp[i] : kp[i - NMEM_];
        sum += __expf(v - m);
    }
    red[tid] = sum; __syncthreads();
    for (int s = 64; s > 0; s >>= 1) {
        if (tid < s) red[tid] += red[tid + s];
        __syncthreads();
    }
    if (tid == 0) { g_kmax[r] = m; g_kinv[r] = 1.0f / red[0]; }
}

// ---------------- context partials ----------------
__global__ void ctx_kernel(const float* __restrict__ memkv) {
    int bh = blockIdx.x;
    int split = blockIdx.y;
    int b = bh >> 2, h = bh & 3;
    int tid = threadIdx.x;
    __shared__ float ks[DH_][65];
    __shared__ float vs[DH_][65];
    int e = tid & 31, dg = tid >> 5;
    float acc[4] = {0.f, 0.f, 0.f, 0.f};
    const float* kbase = g_qkv + ((size_t)b * QKV_C + HID_ + h * DH_) * HW_;
    const float* vbase = g_qkv + ((size_t)b * QKV_C + 2 * HID_ + h * DH_) * HW_;
    int rbase = bh * DH_;
    int n0beg = split * 512;
    for (int n0 = n0beg; n0 < n0beg + 512; n0 += 64) {
        #pragma unroll
        for (int t = 0; t < 8; t++) {
            int i = tid + t * 256;
            int d = i >> 6, j = i & 63;
            float kv = kbase[(size_t)d * HW_ + n0 + j];
            ks[d][j] = __expf(kv - g_kmax[rbase + d]) * g_kinv[rbase + d];
            vs[d][j] = vbase[(size_t)d * HW_ + n0 + j];
        }
        __syncthreads();
        #pragma unroll 4
        for (int j = 0; j < 64; j++) {
            float vv = vs[e][j];
            #pragma unroll
            for (int dd = 0; dd < 4; dd++)
                acc[dd] += ks[dg + dd * 8][j] * vv;
        }
        __syncthreads();
    }
    if (split == 0) {
        #pragma unroll
        for (int j = 0; j < NMEM_; j++) {
            #pragma unroll
            for (int dd = 0; dd < 4; dd++) {
                int d = dg + dd * 8;
                float kk = __expf(memkv[(h * DH_ + d) * NMEM_ + j] - g_kmax[rbase + d]) * g_kinv[rbase + d];
                float vv = memkv[((HEADS_ + h) * DH_ + e) * NMEM_ + j];
                acc[dd] += kk * vv;
            }
        }
    }
    #pragma unroll
    for (int dd = 0; dd < 4; dd++) {
        int d = dg + dd * 8;
        g_ctxp[(size_t)split * (B_ * HEADS_ * DH_ * DH_) + bh * 1024 + d * 32 + e] = acc[dd];
    }
}

__global__ void ctx_reduce() {
    int i = blockIdx.x * blockDim.x + threadIdx.x;
    if (i >= B_ * HEADS_ * DH_ * DH_) return;
    float s = 0.f;
    #pragma unroll
    for (int t = 0; t < NSPLIT_; t++) s += g_ctxp[(size_t)t * (B_ * HEADS_ * DH_ * DH_) + i];
    g_ctx[i] = s;
}

// -------- q softmax + apply context; writes att [b][h][hw][dh] fp16 ---------
__global__ void apply_ctx() {
    int bh = blockIdx.y;
    int b = bh >> 2, h = bh & 3;
    int n = blockIdx.x * 128 + threadIdx.x;
    __shared__ float cs[DH_][DH_ + 1];
    for (int i = threadIdx.x; i < DH_ * DH_; i += 128)
        cs[i >> 5][i & 31] = g_ctx[bh * 1024 + i];
    __syncthreads();
    const float* qp = g_qkv + ((size_t)b * QKV_C + h * DH_) * HW_ + n;
    float qd[DH_];
    float m = -1e30f;
    #pragma unroll
    for (int d = 0; d < DH_; d++) { qd[d] = qp[(size_t)d * HW_]; m = fmaxf(m, qd[d]); }
    float s = 0.f;
    #pragma unroll
    for (int d = 0; d < DH_; d++) { qd[d] = __expf(qd[d] - m); s += qd[d]; }
    float inv = 0.17677669529663687f / s;
    #pragma unroll
    for (int d = 0; d < DH_; d++) qd[d] *= inv;

    uint32_t P[16];
    #pragma unroll
    for (int ep = 0; ep < 16; ep++) {
        float o0 = 0.f, o1 = 0.f;
        #pragma unroll
        for (int d = 0; d < DH_; d++) {
            o0 += cs[d][2 * ep] * qd[d];
            o1 += cs[d][2 * ep + 1] * qd[d];
        }
        __half2 h2 = __floats2half2_rn(o0, o1);
        P[ep] = *(uint32_t*)&h2;
    }
    size_t base = (((size_t)b * HEADS_ + h) * HW_ + n) * DH_;
    #pragma unroll
    for (int t = 0; t < 4; t++)
        *(uint4*)(g_aTf + base + t * 8) = *(uint4*)(P + t * 4);
}

// ---------------- final rms norm ----------------
__global__ void rmsnorm2(const float* __restrict__ g2, float* __restrict__ out) {
    int idx = blockIdx.x * blockDim.x + threadIdx.x;
    if (idx >= NCOLS_) return;
    int b = idx >> 12, hw = idx & (HW_ - 1);
    const float* p = g_o + (size_t)b * C_ * HW_ + hw;
    float ss = 0.f;
    #pragma unroll 8
    for (int c = 0; c < C_; c++) { float v = p[(size_t)c * HW_]; ss += v * v; }
    float sc = 16.0f / fmaxf(sqrtf(ss), 1e-12f);
    float* q = out + (size_t)b * C_ * HW_ + hw;
    #pragma unroll 8
    for (int c = 0; c < C_; c++) q[(size_t)c * HW_] = p[(size_t)c * HW_] * sc * g2[c];
}

// ---------------- launcher ----------------
extern "C" void kernel_launch(void* const* d_in, const int* in_sizes, int n_in,
                              void* d_out, int out_size) {
    const float* x      = (const float*)d_in[0];
    const float* g1     = (const float*)d_in[1];
    const float* mem_kv = (const float*)d_in[2];
    const float* w_qkv  = (const float*)d_in[3];
    const float* w_out  = (const float*)d_in[4];
    const float* b_out  = (const float*)d_in[5];
    const float* g2     = (const float*)d_in[6];
    float* out = (float*)d_out;

    __half *w1hi, *w1lo, *w2hi, *w2lo, *xTf, *aTf;
    float *invs, *qkv, *o;
    cudaGetSymbolAddress((void**)&w1hi, g_w1hi);
    cudaGetSymbolAddress((void**)&w1lo, g_w1lo);
    cudaGetSymbolAddress((void**)&w2hi, g_w2hi);
    cudaGetSymbolAddress((void**)&w2lo, g_w2lo);
    cudaGetSymbolAddress((void**)&xTf,  g_xTf);
    cudaGetSymbolAddress((void**)&aTf,  g_aTf);
    cudaGetSymbolAddress((void**)&invs, g_invs);
    cudaGetSymbolAddress((void**)&qkv,  g_qkv);
    cudaGetSymbolAddress((void**)&o,    g_o);

    cudaFuncSetAttribute(gemm_mma, cudaFuncAttributeMaxDynamicSharedMemorySize, GSMEM_B);

    prep_w1<<<(QKV_C * C_ + 255) / 256, 256>>>(w_qkv, g1);
    prep_w2<<<(C_ * HID_ + 255) / 256, 256>>>(w_out);
    transpose_norm<<<dim3(HW_ / 32, B_), dim3(32, 8)>>>(x);
    // qkv = (w*g1*16) @ x, scaled by 1/||x_col||
    gemm_mma<<<dim3(HW_ / 128, QKV_C / 128, B_), 256, GSMEM_B>>>(
        w1hi, w1lo, xTf, qkv, C_, C_, C_, 1L,
        (long)HW_ * C_, (long)QKV_C * HW_, invs, nullptr);
    kstats<<<NROWS_K, 128>>>(mem_kv);
    ctx_kernel<<<dim3(B_ * HEADS_, NSPLIT_), 256>>>(mem_kv);
    ctx_reduce<<<(B_ * HEADS_ * DH_ * DH_ + 255) / 256, 256>>>();
    apply_ctx<<<dim3(HW_ / 128, B_ * HEADS_), 128>>>();
    // o = w_out @ att + b_out  (att layout [b][h][hw][dh]: rsB=32, csB=HW_)
    gemm_mma<<<dim3(HW_ / 128, C_ / 128, B_), 256, GSMEM_B>>>(
        w2hi, w2lo, aTf, o, HID_, HID_, DH_, (long)HW_,
        (long)HW_ * HID_, (long)C_ * HW_, nullptr, b_out);
    rmsnorm2<<<(NCOLS_ + 255) / 256, 256>>>(g2, out);
}